// round 15
// baseline (speedup 1.0000x reference)
#include <cuda_runtime.h>
#include <cstdint>

// FeedForwardNet_72335839199562 — NEAT feed-forward DAG scan, v4.
// Binder identified in R11: L1tex wavefront BW, 16x duplicated W reads
// (16 warps x same 12 W rows = 98KB L1/chunk = 768cyc vs 384 FMA budget).
// v4 halves duplication: 8 warps x 4 batch rows each (TB=32, 128 CTAs).
//   per chunk/SM: FMA 256 cyc == W-L1 256 cyc (co-balanced), LDS 128 cyc.
// Acts: evaluated cols in 192KB smem (warp-private rows, LDS.128);
//       input cols held ENTIRELY in registers (64 regs/thread, loaded once)
//       -> zero part-A act traffic. W first-touch hidden by warp-0
//       prefetch.global.L1 one chunk ahead. Packed fma.rn.f32x2 throughout.
// Per group G=8: dense chunks -> butterfly reduce -> serial triangular tail
// (redundant on all lanes; in-group 8x8 W block double-buffered in smem).

#define N_IN    512
#define N_NODES 2048
#define N_EVAL  1536
#define N_OUT   256
#define TB      32
#define G       8
#define NGROUPS (N_EVAL / G)     // 192
#define THREADS 256              // 8 warps; warp w owns rows 4w..4w+3
#define EVS     1536             // smem row stride (floats)

typedef unsigned long long ull;

__device__ __forceinline__ float sigmoid5(float z) {
    float t = fminf(fmaxf(5.0f * z, -60.0f), 60.0f);
    return 1.0f / (1.0f + __expf(-t));
}

__device__ __forceinline__ ull ffma2(ull a, ull b, ull c) {
    ull d;
    asm("fma.rn.f32x2 %0, %1, %2, %3;" : "=l"(d) : "l"(a), "l"(b), "l"(c));
    return d;
}
__device__ __forceinline__ float lo32(ull v) { return __uint_as_float((unsigned)v); }
__device__ __forceinline__ float hi32(ull v) { return __uint_as_float((unsigned)(v >> 32)); }

__device__ __forceinline__ void l1_prefetch(const float* p) {
    asm volatile("prefetch.global.L1 [%0];" :: "l"(p));
}

__global__ __launch_bounds__(THREADS, 1)
void neat_scan_kernel(const float* __restrict__ x,
                      const float* __restrict__ W,
                      const float* __restrict__ b,
                      float* __restrict__ out)
{
    extern __shared__ float sEval[];            // [TB][EVS] evaluated acts
    __shared__ float sWblk[2][G][G + 1];        // in-group W block, dbl-buf

    const int tid  = threadIdx.x;
    const int warp = tid >> 5;
    const int lane = tid & 31;
    const int rowBase = blockIdx.x * TB;

    // ---- x resident in registers: 4 rows x 4 chunks x (lo,hi) ull -------
    ull xlo[4][4], xhi[4][4];
    #pragma unroll
    for (int r = 0; r < 4; ++r) {
        const float* xr = x + (size_t)(rowBase + warp * 4 + r) * N_IN;
        #pragma unroll
        for (int c = 0; c < 4; ++c) {
            const ulonglong2 v = *(const ulonglong2*)(xr + c * 128 + lane * 4);
            xlo[r][c] = v.x;
            xhi[r][c] = v.y;
        }
    }

    // ---- zero evaluated-act store ---------------------------------------
    {
        float4* p = (float4*)sEval;
        const float4 z4 = make_float4(0.f, 0.f, 0.f, 0.f);
        for (int e = tid; e < TB * EVS / 4; e += THREADS) p[e] = z4;
    }
    // stage in-group W block for group 0
    if (tid < G * G) {
        int r = tid / G, c = tid % G;
        sWblk[0][r][c] = W[(size_t)r * N_NODES + (N_IN + c)];
    }
    // prefetch group 0 chunk 0 of W (8 rows x 4 lines = 32 lines, 1/lane)
    if (warp == 0)
        l1_prefetch(W + (size_t)(lane >> 2) * N_NODES + (lane & 3) * 32);
    __syncthreads();

    float* ev0 = sEval + (warp * 4 + 0) * EVS;
    float* ev1 = sEval + (warp * 4 + 1) * EVS;
    float* ev2 = sEval + (warp * 4 + 2) * EVS;
    float* ev3 = sEval + (warp * 4 + 3) * EVS;

    // ---- sequential scan over node groups -------------------------------
    for (int grp = 0; grp < NGROUPS; ++grp) {
        const int ib = grp * G;
        const float* Wg = W + (size_t)ib * N_NODES;
        const int nB  = (ib + 127) & ~127;       // part-B cols (rounded; over-
        const int nLW = N_IN + nB;               // read hits zeroed acts)

        ull acc[4][G];
        #pragma unroll
        for (int r = 0; r < 4; ++r)
            #pragma unroll
            for (int g = 0; g < G; ++g) acc[r][g] = 0ull;

        // --- part A: input cols, acts from registers --------------------
        #pragma unroll
        for (int c = 0; c < 4; ++c) {
            const int colW = c * 128 + lane * 4;
            if (warp == 0) {                     // prefetch next chunk's W
                const int nc = (c + 1) * 128;
                if (nc < nLW)
                    l1_prefetch(Wg + (size_t)(lane >> 2) * N_NODES + nc + (lane & 3) * 32);
            }
            #pragma unroll
            for (int g = 0; g < G; ++g) {
                const ulonglong2 wv = *(const ulonglong2*)(Wg + (size_t)g * N_NODES + colW);
                acc[0][g] = ffma2(wv.x, xlo[0][c], acc[0][g]);
                acc[0][g] = ffma2(wv.y, xhi[0][c], acc[0][g]);
                acc[1][g] = ffma2(wv.x, xlo[1][c], acc[1][g]);
                acc[1][g] = ffma2(wv.y, xhi[1][c], acc[1][g]);
                acc[2][g] = ffma2(wv.x, xlo[2][c], acc[2][g]);
                acc[2][g] = ffma2(wv.y, xhi[2][c], acc[2][g]);
                acc[3][g] = ffma2(wv.x, xlo[3][c], acc[3][g]);
                acc[3][g] = ffma2(wv.y, xhi[3][c], acc[3][g]);
            }
        }

        // --- part B: evaluated cols, acts from smem ----------------------
        #pragma unroll 1
        for (int base = 0; base < nB; base += 128) {
            const int j = base + lane * 4;
            const ulonglong2 a0 = *(const ulonglong2*)(ev0 + j);
            const ulonglong2 a1 = *(const ulonglong2*)(ev1 + j);
            const ulonglong2 a2 = *(const ulonglong2*)(ev2 + j);
            const ulonglong2 a3 = *(const ulonglong2*)(ev3 + j);
            if (warp == 0) {
                const int nc = N_IN + base + 128;
                if (nc < nLW)
                    l1_prefetch(Wg + (size_t)(lane >> 2) * N_NODES + nc + (lane & 3) * 32);
            }
            const int colW = N_IN + j;
            #pragma unroll
            for (int g = 0; g < G; ++g) {
                const ulonglong2 wv = *(const ulonglong2*)(Wg + (size_t)g * N_NODES + colW);
                acc[0][g] = ffma2(wv.x, a0.x, acc[0][g]);
                acc[0][g] = ffma2(wv.y, a0.y, acc[0][g]);
                acc[1][g] = ffma2(wv.x, a1.x, acc[1][g]);
                acc[1][g] = ffma2(wv.y, a1.y, acc[1][g]);
                acc[2][g] = ffma2(wv.x, a2.x, acc[2][g]);
                acc[2][g] = ffma2(wv.y, a2.y, acc[2][g]);
                acc[3][g] = ffma2(wv.x, a3.x, acc[3][g]);
                acc[3][g] = ffma2(wv.y, a3.y, acc[3][g]);
            }
        }

        // --- fold packed halves, butterfly reduce, add bias --------------
        float s[4][G];
        #pragma unroll
        for (int g = 0; g < G; ++g) {
            const float bg = b[ib + g];
            #pragma unroll
            for (int r = 0; r < 4; ++r) {
                float v = lo32(acc[r][g]) + hi32(acc[r][g]);
                #pragma unroll
                for (int sh = 16; sh > 0; sh >>= 1)
                    v += __shfl_xor_sync(0xffffffffu, v, sh);
                s[r][g] = v + bg;
            }
        }

        // --- serial in-group triangular tail (redundant on all lanes) ----
        const float (*blk)[G + 1] = sWblk[grp & 1];
        #pragma unroll
        for (int g = 0; g < G; ++g) {
            float o[4];
            #pragma unroll
            for (int r = 0; r < 4; ++r) o[r] = sigmoid5(s[r][g]);
            #pragma unroll
            for (int g2 = g + 1; g2 < G; ++g2) {
                const float wt = blk[g2][g];
                #pragma unroll
                for (int r = 0; r < 4; ++r) s[r][g2] = fmaf(wt, o[r], s[r][g2]);
            }
            if (lane == 0) {
                ev0[ib + g] = o[0];
                ev1[ib + g] = o[1];
                ev2[ib + g] = o[2];
                ev3[ib + g] = o[3];
            }
        }

        // --- prep next group: stage W block + prefetch its chunk 0 -------
        const int ibn = ib + G;
        if (ibn < N_EVAL) {
            if (tid < G * G) {
                int r = tid / G, c = tid % G;
                sWblk[(grp + 1) & 1][r][c] =
                    W[(size_t)(ibn + r) * N_NODES + (N_IN + ibn + c)];
            }
            if (warp == 0)
                l1_prefetch(W + (size_t)(ibn + (lane >> 2)) * N_NODES + (lane & 3) * 32);
        }
        __syncthreads();   // publish sWblk (dbl-buffered); keep W lockstep
    }

    // ---- write output: last N_OUT evaluated cols ------------------------
    const int OUT_BASE = EVS - N_OUT;   // 1280
    for (int e = tid; e < TB * N_OUT; e += THREADS) {
        int r = e / N_OUT, c = e % N_OUT;
        out[(size_t)(rowBase + r) * N_OUT + c] = sEval[r * EVS + OUT_BASE + c];
    }
}

extern "C" void kernel_launch(void* const* d_in, const int* in_sizes, int n_in,
                              void* d_out, int out_size)
{
    const float* x = (const float*)d_in[0];   // [4096, 512]
    const float* W = (const float*)d_in[1];   // [1536, 2048]
    const float* b = (const float*)d_in[2];   // [1536]
    float* out = (float*)d_out;               // [4096, 256]

    const size_t smem = (size_t)TB * EVS * sizeof(float);   // 192 KB
    cudaFuncSetAttribute(neat_scan_kernel,
                         cudaFuncAttributeMaxDynamicSharedMemorySize, (int)smem);
    neat_scan_kernel<<<4096 / TB, THREADS, smem>>>(x, W, b, out);
}

// round 17
// speedup vs baseline: 2.3705x; 2.3705x over previous
#include <cuda_runtime.h>
#include <cuda_bf16.h>
#include <cstdint>

// FeedForwardNet — v7: block-scan on legacy tensor path (mma.sync bf16,
// sm_103-base ISA; tcgen05 is unavailable: harness ptxas targets sm_103).
// 12 stages x 128 nodes. Grid 128 CTAs x 32 batch rows, 256 threads.
// Stage k: Z[32,128] = Ah*Wh^T + Ah*Wl^T + Al*Wh^T over K=512+128k
// (split-bf16, fp32 accum, cp.async double-buffered K-chunks of 64),
// then warp-0 register triangular solve (f32x2), acts re-split bf16 hi/lo.

#define N_IN    512
#define N_NODES 2048
#define N_EVAL  1536
#define B_ROWS  4096
#define MT      32
#define NT      128
#define KC      64
#define GT      256
#define ZS      130
#define WTS     130

#define BUFSZ   40960         // Ah 4K | Al 4K | Wh 16K | Wl 16K
#define OFF_WT  81920         // 128 x 130 f32 transposed in-block W
#define OFF_Z   148480        // 32 x 130 f32
#define OFF_B   165120        // 128 f32 bias
#define SMEM_TOTAL 165632

#define SWZ(o) ((o) ^ (((o) >> 3) & 0x70))

typedef unsigned long long ull;

__device__ __align__(16) __nv_bfloat16 g_ah[B_ROWS * N_NODES];
__device__ __align__(16) __nv_bfloat16 g_al[B_ROWS * N_NODES];
__device__ __align__(16) __nv_bfloat16 g_wh[N_EVAL * N_NODES];
__device__ __align__(16) __nv_bfloat16 g_wl[N_EVAL * N_NODES];

__device__ __forceinline__ uint32_t smem_u32(const void* p) {
    uint32_t a;
    asm("{ .reg .u64 t; cvta.to.shared.u64 t, %1; cvt.u32.u64 %0, t; }" : "=r"(a) : "l"(p));
    return a;
}
__device__ __forceinline__ float sigmoid5(float z) {
    float t = fminf(fmaxf(5.0f * z, -60.0f), 60.0f);
    return 1.0f / (1.0f + __expf(-t));
}
__device__ __forceinline__ ull ffma2(ull a, ull b, ull c) {
    ull d;
    asm("fma.rn.f32x2 %0, %1, %2, %3;" : "=l"(d) : "l"(a), "l"(b), "l"(c));
    return d;
}
__device__ __forceinline__ float lo32(ull v) { return __uint_as_float((unsigned)v); }
__device__ __forceinline__ float hi32(ull v) { return __uint_as_float((unsigned)(v >> 32)); }
__device__ __forceinline__ ull pack2(float lo, float hi) {
    ull d;
    asm("mov.b64 %0, {%1, %2};" : "=l"(d) : "r"(__float_as_uint(lo)), "r"(__float_as_uint(hi)));
    return d;
}
__device__ __forceinline__ uint32_t cvt_bf16x2(float lo, float hi) {
    uint32_t r;   // first PTX source -> upper half
    asm("cvt.rn.bf16x2.f32 %0, %1, %2;" : "=r"(r) : "f"(hi), "f"(lo));
    return r;
}
__device__ __forceinline__ uint32_t bfpack(__nv_bfloat16 a, __nv_bfloat16 b) {
    __nv_bfloat162 t(a, b);
    return *reinterpret_cast<uint32_t*>(&t);
}
__device__ __forceinline__ void ldm_x4(uint32_t* r, uint32_t addr) {
    asm volatile("ldmatrix.sync.aligned.m8n8.x4.shared.b16 {%0,%1,%2,%3}, [%4];"
                 : "=r"(r[0]), "=r"(r[1]), "=r"(r[2]), "=r"(r[3]) : "r"(addr));
}
__device__ __forceinline__ void mma16816(float* d, const uint32_t* a,
                                         uint32_t b0, uint32_t b1) {
    asm volatile(
        "mma.sync.aligned.m16n8k16.row.col.f32.bf16.bf16.f32 "
        "{%0,%1,%2,%3}, {%4,%5,%6,%7}, {%8,%9}, {%0,%1,%2,%3};"
        : "+f"(d[0]), "+f"(d[1]), "+f"(d[2]), "+f"(d[3])
        : "r"(a[0]), "r"(a[1]), "r"(a[2]), "r"(a[3]), "r"(b0), "r"(b1));
}
__device__ __forceinline__ void cpa16(uint32_t dst, const void* src) {
    asm volatile("cp.async.cg.shared.global [%0], [%1], 16;" :: "r"(dst), "l"(src));
}
#define CP_COMMIT() asm volatile("cp.async.commit_group;" ::: "memory")
#define CP_WAIT0()  asm volatile("cp.async.wait_group 0;" ::: "memory")

// ---- prep: split W and x into bf16 hi/lo ---------------------------------
__global__ void prep_kernel(const float* __restrict__ x, const float* __restrict__ W)
{
    const int stride = gridDim.x * blockDim.x;
    for (int i = blockIdx.x * blockDim.x + threadIdx.x; i < N_EVAL * N_NODES; i += stride) {
        float w = W[i];
        __nv_bfloat16 h = __float2bfloat16(w);
        g_wh[i] = h;
        g_wl[i] = __float2bfloat16(w - __bfloat162float(h));
    }
    for (int i = blockIdx.x * blockDim.x + threadIdx.x; i < B_ROWS * N_IN; i += stride) {
        int r = i >> 9, c = i & (N_IN - 1);
        float v = x[i];
        __nv_bfloat16 h = __float2bfloat16(v);
        g_ah[(size_t)r * N_NODES + c] = h;
        g_al[(size_t)r * N_NODES + c] = __float2bfloat16(v - __bfloat162float(h));
    }
}

// ---- per-chunk async tile loader (Ah|Al|Wh|Wl, SW128) --------------------
__device__ __forceinline__ void load_chunk(uint32_t sbase, int p, int m0, int e0, int c)
{
    const int tid = threadIdx.x;
    const int colBase = c * KC;
    const uint32_t dbase = sbase + (uint32_t)p * BUFSZ;
    #pragma unroll
    for (int i = 0; i < 10; ++i) {
        const int lin = tid + i * GT;          // 0..2559 16B transfers
        const __nv_bfloat16* src;
        uint32_t dst;
        if (lin < 256) {
            int row = lin >> 3, seg = lin & 7;
            src = g_ah + (size_t)(m0 + row) * N_NODES + colBase + seg * 8;
            dst = dbase + SWZ((uint32_t)(row * 128 + seg * 16));
        } else if (lin < 512) {
            int w = lin - 256, row = w >> 3, seg = w & 7;
            src = g_al + (size_t)(m0 + row) * N_NODES + colBase + seg * 8;
            dst = dbase + 4096u + SWZ((uint32_t)(row * 128 + seg * 16));
        } else if (lin < 1536) {
            int w = lin - 512, row = w >> 3, seg = w & 7;
            src = g_wh + (size_t)(e0 + row) * N_NODES + colBase + seg * 8;
            dst = dbase + 8192u + SWZ((uint32_t)(row * 128 + seg * 16));
        } else {
            int w = lin - 1536, row = w >> 3, seg = w & 7;
            src = g_wl + (size_t)(e0 + row) * N_NODES + colBase + seg * 8;
            dst = dbase + 24576u + SWZ((uint32_t)(row * 128 + seg * 16));
        }
        cpa16(dst, src);
    }
}

// ---- one stage: GEMM over prior cols + fused triangular solve ------------
__global__ __launch_bounds__(GT, 1)
void stage_kernel(const float* __restrict__ W, const float* __restrict__ b,
                  float* __restrict__ out, int k)
{
    extern __shared__ char smem[];
    const uint32_t sbase = smem_u32(smem);
    const int tid  = threadIdx.x;
    const int lane = tid & 31;
    const int wrp  = tid >> 5;
    const int m0 = blockIdx.x * MT;
    const int e0 = k * NT;
    const int node0 = N_IN + e0;
    const int nchunks = (N_IN + e0) / KC;      // 8 + 2k

    const int mrow0 = (wrp & 1) * 16;          // warp M offset
    const int nbase = (wrp >> 1) * 32;         // warp N offset

    float acc[4][4];
    #pragma unroll
    for (int t = 0; t < 4; ++t)
        #pragma unroll
        for (int j = 0; j < 4; ++j) acc[t][j] = 0.0f;

    // preload chunk 0
    load_chunk(sbase, 0, m0, e0, 0);
    CP_COMMIT();

    // stage in-block W (fp32, transposed) + bias — overlaps preload
    float* sWT = (float*)(smem + OFF_WT);
    #pragma unroll
    for (int i = 0; i < 16; ++i) {
        const int lin = tid + i * GT;          // 0..4095 float4
        const int r = lin >> 5, c4 = lin & 31;
        const float4 v = *(const float4*)(W + (size_t)(e0 + r) * N_NODES + node0 + c4 * 4);
        sWT[(c4 * 4 + 0) * WTS + r] = v.x;
        sWT[(c4 * 4 + 1) * WTS + r] = v.y;
        sWT[(c4 * 4 + 2) * WTS + r] = v.z;
        sWT[(c4 * 4 + 3) * WTS + r] = v.w;
    }
    if (tid < NT) ((float*)(smem + OFF_B))[tid] = b[e0 + tid];

    // ---- K loop: double-buffered cp.async + 3-pass mma ------------------
    const int lr = lane & 15, lk = lane >> 4;
    for (int c = 0; c < nchunks; ++c) {
        CP_WAIT0();
        __syncthreads();                        // buf (c&1) ready for all
        if (c + 1 < nchunks) { load_chunk(sbase, (c + 1) & 1, m0, e0, c + 1); CP_COMMIT(); }

        const uint32_t bb  = sbase + (uint32_t)(c & 1) * BUFSZ;
        const uint32_t bAh = bb, bAl = bb + 4096u, bWh = bb + 8192u, bWl = bb + 24576u;
        #pragma unroll
        for (int kk = 0; kk < 4; ++kk) {
            const uint32_t koff  = kk * 32 + lk * 16;
            const uint32_t aoff  = SWZ((uint32_t)((mrow0 + lr) * 128) + koff);
            const uint32_t boff0 = SWZ((uint32_t)((nbase + lr) * 128) + koff);
            const uint32_t boff1 = SWZ((uint32_t)((nbase + 16 + lr) * 128) + koff);
            uint32_t ah[4], al[4], w0[4], w1[4], v0[4], v1[4];
            ldm_x4(ah, bAh + aoff);
            ldm_x4(al, bAl + aoff);
            ldm_x4(w0, bWh + boff0);
            ldm_x4(w1, bWh + boff1);
            ldm_x4(v0, bWl + boff0);
            ldm_x4(v1, bWl + boff1);
            mma16816(acc[0], ah, w0[0], w0[2]);   // Ah*Wh
            mma16816(acc[1], ah, w0[1], w0[3]);
            mma16816(acc[2], ah, w1[0], w1[2]);
            mma16816(acc[3], ah, w1[1], w1[3]);
            mma16816(acc[0], ah, v0[0], v0[2]);   // Ah*Wl
            mma16816(acc[1], ah, v0[1], v0[3]);
            mma16816(acc[2], ah, v1[0], v1[2]);
            mma16816(acc[3], ah, v1[1], v1[3]);
            mma16816(acc[0], al, w0[0], w0[2]);   // Al*Wh
            mma16816(acc[1], al, w0[1], w0[3]);
            mma16816(acc[2], al, w1[0], w1[2]);
            mma16816(acc[3], al, w1[1], w1[3]);
        }
    }

    // ---- accumulators -> smem Z -----------------------------------------
    {
        float* sZ = (float*)(smem + OFF_Z);
        const int qr = lane >> 2, qc = (lane & 3) * 2;
        #pragma unroll
        for (int t = 0; t < 4; ++t) {
            const int cc = nbase + t * 8 + qc;
            *(float2*)(sZ + (mrow0 + qr) * ZS + cc)     = make_float2(acc[t][0], acc[t][1]);
            *(float2*)(sZ + (mrow0 + qr + 8) * ZS + cc) = make_float2(acc[t][2], acc[t][3]);
        }
    }
    __syncthreads();

    // ---- solve: 32 threads, one batch row each --------------------------
    if (tid < MT) {
        const float* zrow = (const float*)(smem + OFF_Z) + tid * ZS;
        const float* sBias = (const float*)(smem + OFF_B);
        ull z2[64];
        #pragma unroll
        for (int j = 0; j < 64; ++j) z2[j] = *(const ull*)(zrow + 2 * j);

        #pragma unroll
        for (int g = 0; g < NT; ++g) {
            const int p = g >> 1;
            const float zg = (g & 1) ? hi32(z2[p]) : lo32(z2[p]);
            const float o = sigmoid5(zg + sBias[g]);
            const ull o2 = pack2(o, o);
            if ((g & 1) == 0) {
                z2[p] = pack2(o, hi32(z2[p]));
                const ull w2 = pack2(0.0f, sWT[g * WTS + g + 1]);
                z2[p] = ffma2(w2, o2, z2[p]);
            } else {
                z2[p] = pack2(lo32(z2[p]), o);
            }
            #pragma unroll
            for (int q = p + 1; q < 64; ++q) {
                const ull w2 = *(const ull*)(sWT + g * WTS + 2 * q);
                z2[q] = ffma2(w2, o2, z2[q]);
            }
        }

        // ---- writeback ---------------------------------------------------
        const int row = m0 + tid;
        if (k < 11) {
            __nv_bfloat16* ph = g_ah + (size_t)row * N_NODES + node0;
            __nv_bfloat16* pl = g_al + (size_t)row * N_NODES + node0;
            #pragma unroll
            for (int s = 0; s < 16; ++s) {
                uint32_t hw[4], lw[4];
                #pragma unroll
                for (int j = 0; j < 4; ++j) {
                    const float a = lo32(z2[s * 4 + j]), c2 = hi32(z2[s * 4 + j]);
                    const __nv_bfloat16 ah = __float2bfloat16(a), ch = __float2bfloat16(c2);
                    hw[j] = bfpack(ah, ch);
                    lw[j] = cvt_bf16x2(a - __bfloat162float(ah), c2 - __bfloat162float(ch));
                }
                *(uint4*)(ph + 8 * s) = make_uint4(hw[0], hw[1], hw[2], hw[3]);
                *(uint4*)(pl + 8 * s) = make_uint4(lw[0], lw[1], lw[2], lw[3]);
            }
        }
        if (k >= 10) {
            float* po = out + (size_t)row * 256 + (node0 - 1792);
            #pragma unroll
            for (int t = 0; t < 32; ++t)
                *(float4*)(po + 4 * t) = make_float4(lo32(z2[2 * t]), hi32(z2[2 * t]),
                                                     lo32(z2[2 * t + 1]), hi32(z2[2 * t + 1]));
        }
    }
}

extern "C" void kernel_launch(void* const* d_in, const int* in_sizes, int n_in,
                              void* d_out, int out_size)
{
    const float* x = (const float*)d_in[0];   // [4096, 512]
    const float* W = (const float*)d_in[1];   // [1536, 2048]
    const float* b = (const float*)d_in[2];   // [1536]
    float* out = (float*)d_out;               // [4096, 256]

    cudaFuncSetAttribute(stage_kernel,
                         cudaFuncAttributeMaxDynamicSharedMemorySize, SMEM_TOTAL);
    prep_kernel<<<512, 256>>>(x, W);
    for (int k = 0; k < 12; ++k)
        stage_kernel<<<B_ROWS / MT, GT, SMEM_TOTAL>>>(W, b, out, k);
}